// round 7
// baseline (speedup 1.0000x reference)
#include <cuda_runtime.h>
#include <cstdint>
#include <cstddef>

#define NTOK 131072
constexpr size_t NT = (size_t)NTOK;
constexpr size_t OFF_XW    = 0;
constexpr size_t OFF_T     = NT * 256;
constexpr size_t OFF_QKV   = NT * 512;
constexpr size_t OFF_ATTNO = NT * 1280;
constexpr size_t OFF_XW2   = NT * 1536;
constexpr size_t OFF_F     = NT * 1792;
constexpr size_t OFF_H     = NT * 2048;
constexpr size_t OFF_BT_QKV = NT * 3072;           // 768x256
constexpr size_t OFF_BT_OUT = OFF_BT_QKV + 196608; // 256x256
constexpr size_t OFF_BT_W1  = OFF_BT_OUT + 65536;  // 1024x256
constexpr size_t OFF_BT_W2  = OFF_BT_W1 + 262144;  // 256x1024
__device__ float g_scratch[OFF_BT_W2 + 262144];

__device__ __forceinline__ float rndt(float x) {   // round to tf32, keep as fp32
    uint32_t u; asm("cvt.rna.tf32.f32 %0, %1;" : "=r"(u) : "f"(x));
    return __uint_as_float(u);
}
__device__ __forceinline__ uint32_t smem_u32(const void* p) {
    uint32_t a;
    asm("{.reg .u64 t; cvta.to.shared.u64 t, %1; cvt.u32.u64 %0, t;}" : "=r"(a) : "l"(p));
    return a;
}
__device__ __forceinline__ void cpa16(uint32_t dst, const float* src) {
    asm volatile("cp.async.ca.shared.global [%0], [%1], 16;" :: "r"(dst), "l"(src));
}
__device__ __forceinline__ void mma8(float* d, const uint32_t* a, const uint32_t* b) {
    asm volatile(
        "mma.sync.aligned.m16n8k8.row.col.f32.tf32.tf32.f32 "
        "{%0,%1,%2,%3},{%4,%5,%6,%7},{%8,%9},{%0,%1,%2,%3};"
        : "+f"(d[0]), "+f"(d[1]), "+f"(d[2]), "+f"(d[3])
        : "r"(a[0]), "r"(a[1]), "r"(a[2]), "r"(a[3]), "r"(b[0]), "r"(b[1]));
}

// ---------------- weight transpose BT[n][k] = round_tf32(B[k][n]) --------
__global__ void __launch_bounds__(256) k_transpose(
    const float* __restrict__ B, float* __restrict__ BT, int K, int N)
{
    __shared__ float t[32][33];
    int kb = blockIdx.y * 32, nb = blockIdx.x * 32;
    int tx = threadIdx.x & 31, ty = threadIdx.x >> 5;
    for (int i = ty; i < 32; i += 8) t[i][tx] = B[(size_t)(kb + i) * N + nb + tx];
    __syncthreads();
    for (int i = ty; i < 32; i += 8) BT[(size_t)(nb + i) * K + kb + tx] = rndt(t[tx][i]);
}

// ---------------- gather / scatter NCHW <-> token-major ----------------
__global__ void __launch_bounds__(256) k_gather(const float* __restrict__ x)
{
    __shared__ float sm[256][33];
    int tid = threadIdx.x, bi = blockIdx.x;
    int dc = bi & 7, w1 = (bi >> 3) & 7, wx = (bi >> 6) & 31, b = bi >> 11;
    const float* xb = x + ((size_t)b * 256 + dc * 32) * 65536 + (size_t)(wx * 8 + w1) * 256;
#pragma unroll
    for (int it = 0; it < 32; ++it) sm[tid][it] = xb[(size_t)it * 65536 + tid];
    __syncthreads();
#pragma unroll
    for (int it = 0; it < 32; ++it) {
        int t = it * 8 + (tid >> 5), dd = tid & 31;
        size_t tok = (((size_t)b * 32 + wx) * 32 + (t >> 3)) * 64 + w1 * 8 + (t & 7);
        g_scratch[OFF_XW + tok * 256 + dc * 32 + dd] = sm[t][dd];
    }
}
__global__ void __launch_bounds__(256) k_scatter(float* __restrict__ out)
{
    __shared__ float sm[256][33];
    int tid = threadIdx.x, bi = blockIdx.x;
    int dc = bi & 7, w1 = (bi >> 3) & 7, wx = (bi >> 6) & 31, b = bi >> 11;
#pragma unroll
    for (int it = 0; it < 32; ++it) {
        int t = it * 8 + (tid >> 5), dd = tid & 31;
        size_t tok = (((size_t)b * 32 + wx) * 32 + (t >> 3)) * 64 + w1 * 8 + (t & 7);
        sm[t][dd] = g_scratch[OFF_T + tok * 256 + dc * 32 + dd];
    }
    __syncthreads();
    float* ob = out + ((size_t)b * 256 + dc * 32) * 65536 + (size_t)(wx * 8 + w1) * 256;
#pragma unroll
    for (int it = 0; it < 32; ++it) ob[(size_t)it * 65536 + tid] = sm[tid][it];
}

// ------- LayerNorm (TWO=1: LN2(LN1(x)); TWO=0: single LN); tf32-rounds out
template <int TWO>
__global__ void __launch_bounds__(256) k_ln(
    const float* __restrict__ src, float* __restrict__ dst,
    const float* __restrict__ g1, const float* __restrict__ b1,
    const float* __restrict__ g2, const float* __restrict__ b2)
{
    __shared__ float sm[8192], sg1[256], sb1[256], sg2[256], sb2[256], st1[32][2], st2[32][2];
    int tid = threadIdx.x;
    size_t base = (size_t)blockIdx.x * 8192;
    sg1[tid] = g1[tid]; sb1[tid] = b1[tid];
    if (TWO) { sg2[tid] = g2[tid]; sb2[tid] = b2[tid]; }
#pragma unroll
    for (int it = 0; it < 32; ++it) sm[it * 256 + tid] = src[base + it * 256 + tid];
    __syncthreads();
    int warp = tid >> 5, lane = tid & 31;
#pragma unroll
    for (int j = 0; j < 4; ++j) {
        int tok = warp * 4 + j;
        float s = 0.f, ss = 0.f;
#pragma unroll
        for (int m = 0; m < 8; ++m) {
            float v = sm[tok * 256 + lane + 32 * m]; s += v; ss += v * v;
        }
#pragma unroll
        for (int o = 16; o > 0; o >>= 1) {
            s += __shfl_xor_sync(~0u, s, o); ss += __shfl_xor_sync(~0u, ss, o);
        }
        float m1 = s * (1.f / 256.f), i1 = rsqrtf(ss * (1.f / 256.f) - m1 * m1 + 1e-5f);
        if (lane == 0) { st1[tok][0] = m1; st1[tok][1] = i1; }
        if (TWO) {
            float s2 = 0.f, ss2 = 0.f;
#pragma unroll
            for (int m = 0; m < 8; ++m) {
                int d = lane + 32 * m;
                float u = (sm[tok * 256 + d] - m1) * i1 * sg1[d] + sb1[d];
                s2 += u; ss2 += u * u;
            }
#pragma unroll
            for (int o = 16; o > 0; o >>= 1) {
                s2 += __shfl_xor_sync(~0u, s2, o); ss2 += __shfl_xor_sync(~0u, ss2, o);
            }
            if (lane == 0) {
                float m2 = s2 * (1.f / 256.f);
                st2[tok][0] = m2; st2[tok][1] = rsqrtf(ss2 * (1.f / 256.f) - m2 * m2 + 1e-5f);
            }
        }
    }
    __syncthreads();
#pragma unroll
    for (int tok = 0; tok < 32; ++tok) {
        float u = (sm[tok * 256 + tid] - st1[tok][0]) * st1[tok][1] * sg1[tid] + sb1[tid];
        if (TWO) u = (u - st2[tok][0]) * st2[tok][1] * sg2[tid] + sb2[tid];
        dst[base + tok * 256 + tid] = rndt(u);
    }
}

// -------- tf32 mma.sync GEMM: C[M,N]=A[M,K]@B, BT=[N,K], A/B pre-rounded.
// tile 128x128, BK=32, 8 warps (warp 32x64), 3-stage cp.async, raw frag loads.
// EPI: 0 none | 1 +RES | 2 round(gelu(+BIAS)) | 3 +BIAS+RES
#define GEMM_SMEM 110592
template <int EPI>
__global__ void __launch_bounds__(256) k_gemm_mma(
    const float* __restrict__ A, const float* __restrict__ BT,
    float* __restrict__ C, const float* __restrict__ RES,
    const float* __restrict__ BIAS, int N, int K)
{
    extern __shared__ float smf[];   // 3 stages x (A[128][36] + B[128][36])
    const int tid = threadIdx.x, lane = tid & 31, wid = tid >> 5;
    const int bm = blockIdx.y << 7, bn = blockIdx.x << 7;
    const int wr = wid & 3, wc = wid >> 2;
    const int g = lane >> 2, q = lane & 3;

    const int lrow = tid >> 3, lkq = (tid & 7) << 2;
    const float* ApG = A  + (size_t)(bm + lrow) * K + lkq;
    const float* BpG = BT + (size_t)(bn + lrow) * K + lkq;
    const uint32_t sBase = smem_u32(smf);
    const uint32_t soff = ((uint32_t)lrow * 36 + (uint32_t)lkq) * 4;

    float acc[2][8][4];
#pragma unroll
    for (int i = 0; i < 2; ++i)
#pragma unroll
        for (int j = 0; j < 8; ++j)
#pragma unroll
            for (int e = 0; e < 4; ++e) acc[i][j][e] = 0.f;

    const int nc = K >> 5;
    // prologue: stages 0,1
#pragma unroll
    for (int p = 0; p < 2; ++p) {
        const uint32_t st = sBase + (uint32_t)p * 36864u;
        const int kc = p << 5;
#pragma unroll
        for (int it = 0; it < 4; ++it) {
            cpa16(st + soff + it * 32 * 36 * 4, ApG + (size_t)(it * 32) * K + kc);
            cpa16(st + 18432u + soff + it * 32 * 36 * 4, BpG + (size_t)(it * 32) * K + kc);
        }
        asm volatile("cp.async.commit_group;" ::: "memory");
    }

    for (int c = 0; c < nc; ++c) {
        if (c + 1 < nc) asm volatile("cp.async.wait_group 1;" ::: "memory");
        else            asm volatile("cp.async.wait_group 0;" ::: "memory");
        __syncthreads();
        if (c + 2 < nc) {
            const uint32_t st = sBase + (uint32_t)((c + 2) % 3) * 36864u;
            const int kc = (c + 2) << 5;
#pragma unroll
            for (int it = 0; it < 4; ++it) {
                cpa16(st + soff + it * 32 * 36 * 4, ApG + (size_t)(it * 32) * K + kc);
                cpa16(st + 18432u + soff + it * 32 * 36 * 4, BpG + (size_t)(it * 32) * K + kc);
            }
            asm volatile("cp.async.commit_group;" ::: "memory");
        }
        const uint32_t* Ab = (const uint32_t*)(smf + (c % 3) * 9216) + (wr << 5) * 36;
        const uint32_t* Bb = (const uint32_t*)(smf + (c % 3) * 9216 + 4608) + (wc << 6) * 36;
#pragma unroll
        for (int ks = 0; ks < 4; ++ks) {
            const int kb = ks << 3;
            uint32_t bf[8][2];
#pragma unroll
            for (int nt = 0; nt < 8; ++nt) {
                bf[nt][0] = Bb[(nt * 8 + g) * 36 + kb + q];
                bf[nt][1] = Bb[(nt * 8 + g) * 36 + kb + 4 + q];
            }
#pragma unroll
            for (int mt = 0; mt < 2; ++mt) {
                uint32_t af[4];
                af[0] = Ab[(mt * 16 + g) * 36 + kb + q];
                af[1] = Ab[(mt * 16 + 8 + g) * 36 + kb + q];
                af[2] = Ab[(mt * 16 + g) * 36 + kb + 4 + q];
                af[3] = Ab[(mt * 16 + 8 + g) * 36 + kb + 4 + q];
#pragma unroll
                for (int nt = 0; nt < 8; ++nt) mma8(acc[mt][nt], af, bf[nt]);
            }
        }
    }

    // epilogue
#pragma unroll
    for (int mt = 0; mt < 2; ++mt) {
#pragma unroll
        for (int nt = 0; nt < 8; ++nt) {
            int row0 = bm + (wr << 5) + mt * 16 + g;
            int col  = bn + (wc << 6) + nt * 8 + q * 2;
            float v00 = acc[mt][nt][0], v01 = acc[mt][nt][1];
            float v10 = acc[mt][nt][2], v11 = acc[mt][nt][3];
            if (EPI == 2 || EPI == 3) {
                float2 bb = *(const float2*)(BIAS + col);
                v00 += bb.x; v01 += bb.y; v10 += bb.x; v11 += bb.y;
            }
            if (EPI == 1 || EPI == 3) {
                float2 r0 = *(const float2*)(RES + (size_t)row0 * N + col);
                float2 r1 = *(const float2*)(RES + (size_t)(row0 + 8) * N + col);
                v00 += r0.x; v01 += r0.y; v10 += r1.x; v11 += r1.y;
            }
            if (EPI == 2) {
                v00 = rndt(v00 * normcdff(v00)); v01 = rndt(v01 * normcdff(v01));
                v10 = rndt(v10 * normcdff(v10)); v11 = rndt(v11 * normcdff(v11));
            }
            *(float2*)(C + (size_t)row0 * N + col)       = make_float2(v00, v01);
            *(float2*)(C + (size_t)(row0 + 8) * N + col) = make_float2(v10, v11);
        }
    }
}

// ---------------- windowed attention (K transposed in SMEM) -------------
#define ATTN_SMEM (12552 * 4)
__global__ void __launch_bounds__(256) k_attn(const float* __restrict__ rpb)
{
    extern __shared__ float sa[];
    float (*sq)[33]  = (float(*)[33])sa;            // 64x33
    float (*skT)[68] = (float(*)[68])(sa + 2112);   // 32x68
    float (*sv)[36]  = (float(*)[36])(sa + 4288);   // 64x36
    float (*sp)[65]  = (float(*)[65])(sa + 6592);   // 64x65
    float* srpb      = sa + 10752;                  // 1800

    int tid = threadIdx.x;
    size_t tokbase = (size_t)blockIdx.x * 64;
    const float* qkv = g_scratch + OFF_QKV;
    float* outp = g_scratch + OFF_ATTNO;
    for (int i = tid; i < 1800; i += 256) srpb[i] = rpb[i];

    int row = tid >> 2, c = tid & 3;
    int ri = row >> 3, rj = row & 7;
    const float sc = 0.17677669529663687f;

    for (int h = 0; h < 8; ++h) {
        __syncthreads();
#pragma unroll
        for (int m = 0; m < 2; ++m) {
            int e = m * 256 + tid, t = e >> 3, d4 = (e & 7) << 2;
            const float* src = qkv + (tokbase + t) * 768 + h * 32 + d4;
            float4 q4 = *(const float4*)src;
            float4 k4 = *(const float4*)(src + 256);
            float4 v4 = *(const float4*)(src + 512);
            sq[t][d4] = q4.x * sc; sq[t][d4 + 1] = q4.y * sc;
            sq[t][d4 + 2] = q4.z * sc; sq[t][d4 + 3] = q4.w * sc;
            skT[d4][t] = k4.x; skT[d4 + 1][t] = k4.y;
            skT[d4 + 2][t] = k4.z; skT[d4 + 3][t] = k4.w;
            *(float4*)&sv[t][d4] = v4;
        }
        __syncthreads();

        float s[16];
#pragma unroll
        for (int j = 0; j < 16; ++j) s[j] = 0.f;
#pragma unroll
        for (int d = 0; d < 32; ++d) {
            float qv = sq[row][d];
#pragma unroll
            for (int m = 0; m < 4; ++m) {
                float4 kk = *(const float4*)&skT[d][c * 16 + m * 4];
                s[m * 4] += qv * kk.x; s[m * 4 + 1] += qv * kk.y;
                s[m * 4 + 2] += qv * kk.z; s[m * 4 + 3] += qv * kk.w;
            }
        }
#pragma unroll
        for (int j = 0; j < 16; ++j) {
            int col = c * 16 + j;
            s[j] += srpb[((ri - (col >> 3) + 7) * 15 + (rj - (col & 7) + 7)) * 8 + h];
        }
        float mx = s[0];
#pragma unroll
        for (int j = 1; j < 16; ++j) mx = fmaxf(mx, s[j]);
        mx = fmaxf(mx, __shfl_xor_sync(~0u, mx, 1));
        mx = fmaxf(mx, __shfl_xor_sync(~0u, mx, 2));
        float sum = 0.f;
#pragma unroll
        for (int j = 0; j < 16; ++j) { s[j] = __expf(s[j] - mx); sum += s[j]; }
        sum += __shfl_xor_sync(~0u, sum, 1);
        sum += __shfl_xor_sync(~0u, sum, 2);
        float inv = 1.f / sum;
#pragma unroll
        for (int j = 0; j < 16; ++j) sp[row][c * 16 + j] = s[j] * inv;
        __syncthreads();

        float o[8];
#pragma unroll
        for (int dd = 0; dd < 8; ++dd) o[dd] = 0.f;
#pragma unroll
        for (int jc = 0; jc < 64; ++jc) {
            float p = sp[row][jc];
            float4 v0 = *(const float4*)&sv[jc][c * 8];
            float4 v1 = *(const float4*)&sv[jc][c * 8 + 4];
            o[0] += p * v0.x; o[1] += p * v0.y; o[2] += p * v0.z; o[3] += p * v0.w;
            o[4] += p * v1.x; o[5] += p * v1.y; o[6] += p * v1.z; o[7] += p * v1.w;
        }
        float* dst = outp + (tokbase + row) * 256 + h * 32 + c * 8;
        *(float4*)dst =
            make_float4(rndt(o[0]), rndt(o[1]), rndt(o[2]), rndt(o[3]));
        *(float4*)(dst + 4) =
            make_float4(rndt(o[4]), rndt(o[5]), rndt(o[6]), rndt(o[7]));
    }
}

// ---------------- host launcher ----------------
extern "C" void kernel_launch(void* const* d_in, const int* in_sizes, int n_in,
                              void* d_out, int out_size)
{
    const float* x     = (const float*)d_in[0];
    const float* ln1_g = (const float*)d_in[1];
    const float* ln1_b = (const float*)d_in[2];
    const float* ln2_g = (const float*)d_in[3];
    const float* ln2_b = (const float*)d_in[4];
    const float* w_qkv = (const float*)d_in[5];
    const float* w_out = (const float*)d_in[6];
    const float* rpb   = (const float*)d_in[7];
    const float* ln3_g = (const float*)d_in[8];
    const float* ln3_b = (const float*)d_in[9];
    const float* w1    = (const float*)d_in[10];
    const float* b1    = (const float*)d_in[11];
    const float* w2    = (const float*)d_in[12];
    const float* b2    = (const float*)d_in[13];
    float* out = (float*)d_out;

    float* S = nullptr;
    cudaGetSymbolAddress((void**)&S, g_scratch);

    cudaFuncSetAttribute(k_gemm_mma<0>, cudaFuncAttributeMaxDynamicSharedMemorySize, GEMM_SMEM);
    cudaFuncSetAttribute(k_gemm_mma<1>, cudaFuncAttributeMaxDynamicSharedMemorySize, GEMM_SMEM);
    cudaFuncSetAttribute(k_gemm_mma<2>, cudaFuncAttributeMaxDynamicSharedMemorySize, GEMM_SMEM);
    cudaFuncSetAttribute(k_gemm_mma<3>, cudaFuncAttributeMaxDynamicSharedMemorySize, GEMM_SMEM);
    cudaFuncSetAttribute(k_attn, cudaFuncAttributeMaxDynamicSharedMemorySize, ATTN_SMEM);

    k_transpose<<<dim3(24, 8), 256>>>(w_qkv, S + OFF_BT_QKV, 256, 768);
    k_transpose<<<dim3(8, 8), 256>>>(w_out, S + OFF_BT_OUT, 256, 256);
    k_transpose<<<dim3(32, 8), 256>>>(w1, S + OFF_BT_W1, 256, 1024);
    k_transpose<<<dim3(8, 32), 256>>>(w2, S + OFF_BT_W2, 1024, 256);

    k_gather<<<4096, 256>>>(x);
    k_ln<1><<<4096, 256>>>(S + OFF_XW, S + OFF_T, ln1_g, ln1_b, ln2_g, ln2_b);
    k_gemm_mma<0><<<dim3(6, 1024), 256, GEMM_SMEM>>>(
        S + OFF_T, S + OFF_BT_QKV, S + OFF_QKV, S, S, 768, 256);
    k_attn<<<2048, 256, ATTN_SMEM>>>(rpb);
    k_gemm_mma<1><<<dim3(2, 1024), 256, GEMM_SMEM>>>(
        S + OFF_ATTNO, S + OFF_BT_OUT, S + OFF_XW2, S + OFF_XW, S, 256, 256);
    k_ln<0><<<4096, 256>>>(S + OFF_XW2, S + OFF_F, ln3_g, ln3_b, ln3_g, ln3_b);
    k_gemm_mma<2><<<dim3(8, 1024), 256, GEMM_SMEM>>>(
        S + OFF_F, S + OFF_BT_W1, S + OFF_H, S, b1, 1024, 256);
    k_gemm_mma<3><<<dim3(2, 1024), 256, GEMM_SMEM>>>(
        S + OFF_H, S + OFF_BT_W2, S + OFF_T, S + OFF_XW2, b2, 256, 1024);
    k_scatter<<<4096, 256>>>(out);
}

// round 9
// speedup vs baseline: 1.0259x; 1.0259x over previous
#include <cuda_runtime.h>
#include <cstdint>
#include <cstddef>

#define NTOK 131072
constexpr size_t NT = (size_t)NTOK;
constexpr size_t OFF_XW    = 0;
constexpr size_t OFF_T     = NT * 256;
constexpr size_t OFF_QKV   = NT * 512;
constexpr size_t OFF_ATTNO = NT * 1280;
constexpr size_t OFF_XW2   = NT * 1536;
constexpr size_t OFF_F     = NT * 1792;
constexpr size_t OFF_H     = NT * 2048;
constexpr size_t OFF_BT_QKV = NT * 3072;           // 768x256
constexpr size_t OFF_BT_OUT = OFF_BT_QKV + 196608; // 256x256
constexpr size_t OFF_BT_W1  = OFF_BT_OUT + 65536;  // 1024x256
constexpr size_t OFF_BT_W2  = OFF_BT_W1 + 262144;  // 256x1024
__device__ float g_scratch[OFF_BT_W2 + 262144];

__device__ __forceinline__ float rndt(float x) {   // round to tf32, keep as fp32
    uint32_t u; asm("cvt.rna.tf32.f32 %0, %1;" : "=r"(u) : "f"(x));
    return __uint_as_float(u);
}
__device__ __forceinline__ uint32_t smem_u32(const void* p) {
    uint32_t a;
    asm("{.reg .u64 t; cvta.to.shared.u64 t, %1; cvt.u32.u64 %0, t;}" : "=r"(a) : "l"(p));
    return a;
}
__device__ __forceinline__ void cpa16(uint32_t dst, const float* src) {
    asm volatile("cp.async.ca.shared.global [%0], [%1], 16;" :: "r"(dst), "l"(src));
}
__device__ __forceinline__ void mma8(float* d, const uint32_t* a, const uint32_t* b) {
    asm volatile(
        "mma.sync.aligned.m16n8k8.row.col.f32.tf32.tf32.f32 "
        "{%0,%1,%2,%3},{%4,%5,%6,%7},{%8,%9},{%0,%1,%2,%3};"
        : "+f"(d[0]), "+f"(d[1]), "+f"(d[2]), "+f"(d[3])
        : "r"(a[0]), "r"(a[1]), "r"(a[2]), "r"(a[3]), "r"(b[0]), "r"(b[1]));
}

// ---------------- weight transpose BT[n][k] = round_tf32(B[k][n]) --------
__global__ void __launch_bounds__(256) k_transpose(
    const float* __restrict__ B, float* __restrict__ BT, int K, int N)
{
    __shared__ float t[32][33];
    int kb = blockIdx.y * 32, nb = blockIdx.x * 32;
    int tx = threadIdx.x & 31, ty = threadIdx.x >> 5;
    for (int i = ty; i < 32; i += 8) t[i][tx] = B[(size_t)(kb + i) * N + nb + tx];
    __syncthreads();
    for (int i = ty; i < 32; i += 8) BT[(size_t)(nb + i) * K + kb + tx] = rndt(t[tx][i]);
}

// ---------------- gather / scatter NCHW <-> token-major ----------------
__global__ void __launch_bounds__(256) k_gather(const float* __restrict__ x)
{
    __shared__ float sm[256][33];
    int tid = threadIdx.x, bi = blockIdx.x;
    int dc = bi & 7, w1 = (bi >> 3) & 7, wx = (bi >> 6) & 31, b = bi >> 11;
    const float* xb = x + ((size_t)b * 256 + dc * 32) * 65536 + (size_t)(wx * 8 + w1) * 256;
#pragma unroll
    for (int it = 0; it < 32; ++it) sm[tid][it] = xb[(size_t)it * 65536 + tid];
    __syncthreads();
#pragma unroll
    for (int it = 0; it < 32; ++it) {
        int t = it * 8 + (tid >> 5), dd = tid & 31;
        size_t tok = (((size_t)b * 32 + wx) * 32 + (t >> 3)) * 64 + w1 * 8 + (t & 7);
        g_scratch[OFF_XW + tok * 256 + dc * 32 + dd] = sm[t][dd];
    }
}
__global__ void __launch_bounds__(256) k_scatter(float* __restrict__ out)
{
    __shared__ float sm[256][33];
    int tid = threadIdx.x, bi = blockIdx.x;
    int dc = bi & 7, w1 = (bi >> 3) & 7, wx = (bi >> 6) & 31, b = bi >> 11;
#pragma unroll
    for (int it = 0; it < 32; ++it) {
        int t = it * 8 + (tid >> 5), dd = tid & 31;
        size_t tok = (((size_t)b * 32 + wx) * 32 + (t >> 3)) * 64 + w1 * 8 + (t & 7);
        sm[t][dd] = g_scratch[OFF_T + tok * 256 + dc * 32 + dd];
    }
    __syncthreads();
    float* ob = out + ((size_t)b * 256 + dc * 32) * 65536 + (size_t)(wx * 8 + w1) * 256;
#pragma unroll
    for (int it = 0; it < 32; ++it) ob[(size_t)it * 65536 + tid] = sm[tid][it];
}

// ------- LayerNorm (TWO=1: LN2(LN1(x)); TWO=0: single LN); tf32-rounds out
template <int TWO>
__global__ void __launch_bounds__(256) k_ln(
    const float* __restrict__ src, float* __restrict__ dst,
    const float* __restrict__ g1, const float* __restrict__ b1,
    const float* __restrict__ g2, const float* __restrict__ b2)
{
    __shared__ float sm[8192], sg1[256], sb1[256], sg2[256], sb2[256], st1[32][2], st2[32][2];
    int tid = threadIdx.x;
    size_t base = (size_t)blockIdx.x * 8192;
    sg1[tid] = g1[tid]; sb1[tid] = b1[tid];
    if (TWO) { sg2[tid] = g2[tid]; sb2[tid] = b2[tid]; }
#pragma unroll
    for (int it = 0; it < 32; ++it) sm[it * 256 + tid] = src[base + it * 256 + tid];
    __syncthreads();
    int warp = tid >> 5, lane = tid & 31;
#pragma unroll
    for (int j = 0; j < 4; ++j) {
        int tok = warp * 4 + j;
        float s = 0.f, ss = 0.f;
#pragma unroll
        for (int m = 0; m < 8; ++m) {
            float v = sm[tok * 256 + lane + 32 * m]; s += v; ss += v * v;
        }
#pragma unroll
        for (int o = 16; o > 0; o >>= 1) {
            s += __shfl_xor_sync(~0u, s, o); ss += __shfl_xor_sync(~0u, ss, o);
        }
        float m1 = s * (1.f / 256.f), i1 = rsqrtf(ss * (1.f / 256.f) - m1 * m1 + 1e-5f);
        if (lane == 0) { st1[tok][0] = m1; st1[tok][1] = i1; }
        if (TWO) {
            float s2 = 0.f, ss2 = 0.f;
#pragma unroll
            for (int m = 0; m < 8; ++m) {
                int d = lane + 32 * m;
                float u = (sm[tok * 256 + d] - m1) * i1 * sg1[d] + sb1[d];
                s2 += u; ss2 += u * u;
            }
#pragma unroll
            for (int o = 16; o > 0; o >>= 1) {
                s2 += __shfl_xor_sync(~0u, s2, o); ss2 += __shfl_xor_sync(~0u, ss2, o);
            }
            if (lane == 0) {
                float m2 = s2 * (1.f / 256.f);
                st2[tok][0] = m2; st2[tok][1] = rsqrtf(ss2 * (1.f / 256.f) - m2 * m2 + 1e-5f);
            }
        }
    }
    __syncthreads();
#pragma unroll
    for (int tok = 0; tok < 32; ++tok) {
        float u = (sm[tok * 256 + tid] - st1[tok][0]) * st1[tok][1] * sg1[tid] + sb1[tid];
        if (TWO) u = (u - st2[tok][0]) * st2[tok][1] * sg2[tid] + sb2[tid];
        dst[base + tok * 256 + tid] = rndt(u);
    }
}

// -------- tf32 mma.sync GEMM: C[M,N]=A[M,K]@B, BT=[N,K], A/B pre-rounded.
// tile 128x128, BK=32, 8 warps (warp 32x64), 2-stage cp.async (R6 structure).
// EPI: 0 none | 1 +RES | 2 round(gelu(+BIAS)) | 3 +BIAS+RES
#define GEMM_SMEM 73728
template <int EPI>
__global__ void __launch_bounds__(256) k_gemm_mma(
    const float* __restrict__ A, const float* __restrict__ BT,
    float* __restrict__ C, const float* __restrict__ RES,
    const float* __restrict__ BIAS, int N, int K)
{
    extern __shared__ float smf[];   // 2 stages x (A[128][36] + B[128][36])
    const int tid = threadIdx.x, lane = tid & 31, wid = tid >> 5;
    const int bm = blockIdx.y << 7, bn = blockIdx.x << 7;
    const int wr = wid & 3, wc = wid >> 2;
    const int g = lane >> 2, q = lane & 3;

    const int lrow = tid >> 3, lkq = (tid & 7) << 2;
    const float* ApG = A  + (size_t)(bm + lrow) * K + lkq;
    const float* BpG = BT + (size_t)(bn + lrow) * K + lkq;
    const uint32_t sBase = smem_u32(smf);
    const uint32_t soff = ((uint32_t)lrow * 36 + (uint32_t)lkq) * 4;

    float acc[2][8][4];
#pragma unroll
    for (int i = 0; i < 2; ++i)
#pragma unroll
        for (int j = 0; j < 8; ++j)
#pragma unroll
            for (int e = 0; e < 4; ++e) acc[i][j][e] = 0.f;

    // prefetch chunk 0
#pragma unroll
    for (int it = 0; it < 4; ++it) {
        cpa16(sBase + soff + it * 32 * 36 * 4, ApG + (size_t)(it * 32) * K);
        cpa16(sBase + 18432u + soff + it * 32 * 36 * 4, BpG + (size_t)(it * 32) * K);
    }
    asm volatile("cp.async.commit_group;" ::: "memory");

    const int nc = K >> 5;
    for (int c = 0; c < nc; ++c) {
        if (c + 1 < nc) {
            const int kc = (c + 1) << 5;
            const uint32_t st = sBase + (uint32_t)((c + 1) & 1) * 36864u;
#pragma unroll
            for (int it = 0; it < 4; ++it) {
                cpa16(st + soff + it * 32 * 36 * 4, ApG + (size_t)(it * 32) * K + kc);
                cpa16(st + 18432u + soff + it * 32 * 36 * 4, BpG + (size_t)(it * 32) * K + kc);
            }
            asm volatile("cp.async.commit_group;" ::: "memory");
            asm volatile("cp.async.wait_group 1;" ::: "memory");
        } else {
            asm volatile("cp.async.wait_group 0;" ::: "memory");
        }
        __syncthreads();

        const uint32_t* Ab = (const uint32_t*)(smf + (c & 1) * 9216) + (wr << 5) * 36;
        const uint32_t* Bb = (const uint32_t*)(smf + (c & 1) * 9216 + 4608) + (wc << 6) * 36;
#pragma unroll
        for (int ks = 0; ks < 4; ++ks) {
            const int kb = ks << 3;
            uint32_t bf[8][2];
#pragma unroll
            for (int nt = 0; nt < 8; ++nt) {
                bf[nt][0] = Bb[(nt * 8 + g) * 36 + kb + q];
                bf[nt][1] = Bb[(nt * 8 + g) * 36 + kb + 4 + q];
            }
#pragma unroll
            for (int mt = 0; mt < 2; ++mt) {
                uint32_t af[4];
                af[0] = Ab[(mt * 16 + g) * 36 + kb + q];
                af[1] = Ab[(mt * 16 + 8 + g) * 36 + kb + q];
                af[2] = Ab[(mt * 16 + g) * 36 + kb + 4 + q];
                af[3] = Ab[(mt * 16 + 8 + g) * 36 + kb + 4 + q];
#pragma unroll
                for (int nt = 0; nt < 8; ++nt) mma8(acc[mt][nt], af, bf[nt]);
            }
        }
        __syncthreads();
    }

    // epilogue
#pragma unroll
    for (int mt = 0; mt < 2; ++mt) {
#pragma unroll
        for (int nt = 0; nt < 8; ++nt) {
            int row0 = bm + (wr << 5) + mt * 16 + g;
            int col  = bn + (wc << 6) + nt * 8 + q * 2;
            float v00 = acc[mt][nt][0], v01 = acc[mt][nt][1];
            float v10 = acc[mt][nt][2], v11 = acc[mt][nt][3];
            if (EPI == 2 || EPI == 3) {
                float2 bb = *(const float2*)(BIAS + col);
                v00 += bb.x; v01 += bb.y; v10 += bb.x; v11 += bb.y;
            }
            if (EPI == 1 || EPI == 3) {
                float2 r0 = *(const float2*)(RES + (size_t)row0 * N + col);
                float2 r1 = *(const float2*)(RES + (size_t)(row0 + 8) * N + col);
                v00 += r0.x; v01 += r0.y; v10 += r1.x; v11 += r1.y;
            }
            if (EPI == 2) {
                v00 = rndt(v00 * normcdff(v00)); v01 = rndt(v01 * normcdff(v01));
                v10 = rndt(v10 * normcdff(v10)); v11 = rndt(v11 * normcdff(v11));
            }
            *(float2*)(C + (size_t)row0 * N + col)       = make_float2(v00, v01);
            *(float2*)(C + (size_t)(row0 + 8) * N + col) = make_float2(v10, v11);
        }
    }
}

// -------- windowed attention: 2 heads per pass, K transposed in SMEM ----
// smem floats: sq[2][64][33]=4224 | skT[2][32][68]=4352 | sv[2][64][36]=4608
//              sp[2][64][68]=8704 | srpb 1800  -> 23688 floats = 94752 B
#define ATTN_SMEM 94752
__global__ void __launch_bounds__(256) k_attn(const float* __restrict__ rpb)
{
    extern __shared__ float sa[];
    float* sqb  = sa;           // [hh*2112 + t*33 + d]
    float* skTb = sa + 4224;    // [hh*2176 + d*68 + t]
    float* svb  = sa + 8576;    // [hh*2304 + t*36 + d]
    float* spb  = sa + 13184;   // [hh*4352 + row*68 + col]  (stride 68: float4-safe)
    float* srpb = sa + 21888;   // [1800]

    int tid = threadIdx.x;
    size_t tokbase = (size_t)blockIdx.x * 64;
    const float* qkv = g_scratch + OFF_QKV;
    float* outp = g_scratch + OFF_ATTNO;
    for (int i = tid; i < 1800; i += 256) srpb[i] = rpb[i];

    int row = tid >> 2, c = tid & 3;
    int ri = row >> 3, rj = row & 7;
    const float sc = 0.17677669529663687f;

    for (int h = 0; h < 8; h += 2) {
        __syncthreads();   // protect smem reuse across passes (incl. srpb fill)
        // load q,k,v for heads h and h+1
#pragma unroll
        for (int m = 0; m < 4; ++m) {
            int e = m * 256 + tid;
            int t = e >> 4, rem = e & 15;
            int hh = rem >> 3, d4 = (rem & 7) << 2;
            const float* src = qkv + (tokbase + t) * 768 + (h + hh) * 32 + d4;
            float4 q4 = *(const float4*)src;
            float4 k4 = *(const float4*)(src + 256);
            float4 v4 = *(const float4*)(src + 512);
            float* sq = sqb + hh * 2112 + t * 33;
            sq[d4] = q4.x * sc; sq[d4 + 1] = q4.y * sc;
            sq[d4 + 2] = q4.z * sc; sq[d4 + 3] = q4.w * sc;
            float* sk = skTb + hh * 2176;
            sk[(d4 + 0) * 68 + t] = k4.x; sk[(d4 + 1) * 68 + t] = k4.y;
            sk[(d4 + 2) * 68 + t] = k4.z; sk[(d4 + 3) * 68 + t] = k4.w;
            *(float4*)(svb + hh * 2304 + t * 36 + d4) = v4;
        }
        __syncthreads();

        // scores + softmax for both heads -> sp[hh]
#pragma unroll
        for (int hh = 0; hh < 2; ++hh) {
            const float* sq = sqb + hh * 2112 + row * 33;
            const float* sk = skTb + hh * 2176;
            float s[16];
#pragma unroll
            for (int j = 0; j < 16; ++j) s[j] = 0.f;
#pragma unroll
            for (int d = 0; d < 32; ++d) {
                float qv = sq[d];
#pragma unroll
                for (int m = 0; m < 4; ++m) {
                    float4 kk = *(const float4*)(sk + d * 68 + c * 16 + m * 4);
                    s[m * 4] += qv * kk.x; s[m * 4 + 1] += qv * kk.y;
                    s[m * 4 + 2] += qv * kk.z; s[m * 4 + 3] += qv * kk.w;
                }
            }
#pragma unroll
            for (int j = 0; j < 16; ++j) {
                int col = c * 16 + j;
                s[j] += srpb[((ri - (col >> 3) + 7) * 15 + (rj - (col & 7) + 7)) * 8 + h + hh];
            }
            float mx = s[0];
#pragma unroll
            for (int j = 1; j < 16; ++j) mx = fmaxf(mx, s[j]);
            mx = fmaxf(mx, __shfl_xor_sync(~0u, mx, 1));
            mx = fmaxf(mx, __shfl_xor_sync(~0u, mx, 2));
            float sum = 0.f;
#pragma unroll
            for (int j = 0; j < 16; ++j) { s[j] = __expf(s[j] - mx); sum += s[j]; }
            sum += __shfl_xor_sync(~0u, sum, 1);
            sum += __shfl_xor_sync(~0u, sum, 2);
            float inv = 1.f / sum;
            float* sp = spb + hh * 4352 + row * 68;
#pragma unroll
            for (int m = 0; m < 4; ++m)
                *(float4*)(sp + c * 16 + m * 4) =
                    make_float4(s[m * 4] * inv, s[m * 4 + 1] * inv,
                                s[m * 4 + 2] * inv, s[m * 4 + 3] * inv);
        }
        __syncthreads();

        // P.V for both heads
#pragma unroll
        for (int hh = 0; hh < 2; ++hh) {
            const float* sp = spb + hh * 4352 + row * 68;
            const float* sv = svb + hh * 2304;
            float o[8];
#pragma unroll
            for (int dd = 0; dd < 8; ++dd) o[dd] = 0.f;
#pragma unroll
            for (int j4 = 0; j4 < 16; ++j4) {
                float4 p4 = *(const float4*)(sp + j4 * 4);
                const float* v0 = sv + (j4 * 4) * 36 + c * 8;
                float4 a0 = *(const float4*)v0,        a1 = *(const float4*)(v0 + 4);
                float4 b0 = *(const float4*)(v0 + 36), b1 = *(const float4*)(v0 + 40);
                float4 c0 = *(const float4*)(v0 + 72), c1 = *(const float4*)(v0 + 76);
                float4 d0 = *(const float4*)(v0 + 108), d1 = *(const float4*)(v0 + 112);
                o[0] += p4.x * a0.x + p4.y * b0.x + p4.z * c0.x + p4.w * d0.x;
                o[1] += p4.x * a0.y + p4.y * b0.y + p4.z * c0.y + p4.w * d0.y;
                o[2] += p4.x * a0.z + p4.y * b0.z + p4.z * c0.z + p4.w * d0.z;
                o[3] += p4.x * a0.w + p4.y * b0.w + p4.z * c0.w + p4.w * d0.w;
                o[4] += p4.x * a1.x + p4.y * b1.x + p4.z * c1.x + p4.w * d1.x;
                o[5] += p4.x * a1.y + p4.y * b1.y + p4.z * c1.y + p4.w * d1.y;
                o[6] += p4.x * a1.z + p4.y * b1.z + p4.z * c1.z + p4.w * d1.z;
                o[7] += p4.x * a1.w + p4.y * b1.w + p4.z * c1.w + p4.w * d1.w;
            }
            float* dst = outp + (tokbase + row) * 256 + (h + hh) * 32 + c * 8;
            *(float4*)dst =
                make_float4(rndt(o[0]), rndt(o[1]), rndt(o[2]), rndt(o[3]));
            *(float4*)(dst + 4) =
                make_float4(rndt(o[4]), rndt(o[5]), rndt(o[6]), rndt(o[7]));
        }
    }
}

// ---------------- host launcher ----------------
extern "C" void kernel_launch(void* const* d_in, const int* in_sizes, int n_in,
                              void* d_out, int out_size)
{
    const float* x     = (const float*)d_in[0];
    const float* ln1_g = (const float*)d_in[1];
    const float* ln1_b = (const float*)d_in[2];
    const float* ln2_g = (const float*)d_in[3];
    const float* ln2_b = (const float*)d_in[4];
    const float* w_qkv = (const float*)d_in[5];
    const float* w_out = (const float*)d_in[6];
    const float* rpb   = (const float*)d_in[7];
    const float* ln3_g = (const float*)d_in[8];
    const float* ln3_b = (const float*)d_in[9];
    const float* w1    = (const float*)d_in[10];
    const float* b1    = (const float*)d_in[11];
    const float* w2    = (const float*)d_in[12];
    const float* b2    = (const float*)d_in[13];
    float* out = (float*)d_out;

    float* S = nullptr;
    cudaGetSymbolAddress((void**)&S, g_scratch);

    cudaFuncSetAttribute(k_gemm_mma<0>, cudaFuncAttributeMaxDynamicSharedMemorySize, GEMM_SMEM);
    cudaFuncSetAttribute(k_gemm_mma<1>, cudaFuncAttributeMaxDynamicSharedMemorySize, GEMM_SMEM);
    cudaFuncSetAttribute(k_gemm_mma<2>, cudaFuncAttributeMaxDynamicSharedMemorySize, GEMM_SMEM);
    cudaFuncSetAttribute(k_gemm_mma<3>, cudaFuncAttributeMaxDynamicSharedMemorySize, GEMM_SMEM);
    cudaFuncSetAttribute(k_attn, cudaFuncAttributeMaxDynamicSharedMemorySize, ATTN_SMEM);

    // order chosen so the profiled launch (#4) is the qkv GEMM
    k_gather<<<4096, 256>>>(x);                                              // 1
    k_ln<1><<<4096, 256>>>(S + OFF_XW, S + OFF_T, ln1_g, ln1_b, ln2_g, ln2_b); // 2
    k_transpose<<<dim3(24, 8), 256>>>(w_qkv, S + OFF_BT_QKV, 256, 768);      // 3
    k_gemm_mma<0><<<dim3(6, 1024), 256, GEMM_SMEM>>>(                        // 4
        S + OFF_T, S + OFF_BT_QKV, S + OFF_QKV, S, S, 768, 256);
    k_transpose<<<dim3(8, 8), 256>>>(w_out, S + OFF_BT_OUT, 256, 256);       // 5
    k_transpose<<<dim3(32, 8), 256>>>(w1, S + OFF_BT_W1, 256, 1024);         // 6
    k_transpose<<<dim3(8, 32), 256>>>(w2, S + OFF_BT_W2, 1024, 256);         // 7
    k_attn<<<2048, 256, ATTN_SMEM>>>(rpb);                                   // 8
    k_gemm_mma<1><<<dim3(2, 1024), 256, GEMM_SMEM>>>(
        S + OFF_ATTNO, S + OFF_BT_OUT, S + OFF_XW2, S + OFF_XW, S, 256, 256);
    k_ln<0><<<4096, 256>>>(S + OFF_XW2, S + OFF_F, ln3_g, ln3_b, ln3_g, ln3_b);
    k_gemm_mma<2><<<dim3(8, 1024), 256, GEMM_SMEM>>>(
        S + OFF_F, S + OFF_BT_W1, S + OFF_H, S, b1, 1024, 256);
    k_gemm_mma<3><<<dim3(2, 1024), 256, GEMM_SMEM>>>(
        S + OFF_H, S + OFF_BT_W2, S + OFF_T, S + OFF_XW2, b2, 256, 1024);
    k_scatter<<<4096, 256>>>(out);
}

// round 10
// speedup vs baseline: 1.0741x; 1.0470x over previous
#include <cuda_runtime.h>
#include <cstdint>
#include <cstddef>

#define NTOK 131072
constexpr size_t NT = (size_t)NTOK;
constexpr size_t OFF_XW    = 0;
constexpr size_t OFF_T     = NT * 256;
constexpr size_t OFF_QKV   = NT * 512;
constexpr size_t OFF_ATTNO = NT * 1280;
constexpr size_t OFF_XW2   = NT * 1536;
constexpr size_t OFF_F     = NT * 1792;
constexpr size_t OFF_H     = NT * 2048;
constexpr size_t OFF_BT_QKV = NT * 3072;           // 768x256
constexpr size_t OFF_BT_OUT = OFF_BT_QKV + 196608; // 256x256
constexpr size_t OFF_BT_W1  = OFF_BT_OUT + 65536;  // 1024x256
constexpr size_t OFF_BT_W2  = OFF_BT_W1 + 262144;  // 256x1024
__device__ float g_scratch[OFF_BT_W2 + 262144];

__device__ __forceinline__ float rndt(float x) {   // round to tf32, keep as fp32
    uint32_t u; asm("cvt.rna.tf32.f32 %0, %1;" : "=r"(u) : "f"(x));
    return __uint_as_float(u);
}
__device__ __forceinline__ uint32_t smem_u32(const void* p) {
    uint32_t a;
    asm("{.reg .u64 t; cvta.to.shared.u64 t, %1; cvt.u32.u64 %0, t;}" : "=r"(a) : "l"(p));
    return a;
}
__device__ __forceinline__ void cpa16(uint32_t dst, const float* src) {
    asm volatile("cp.async.ca.shared.global [%0], [%1], 16;" :: "r"(dst), "l"(src));
}
__device__ __forceinline__ void mma8(float* d, const uint32_t* a, const uint32_t* b) {
    asm volatile(
        "mma.sync.aligned.m16n8k8.row.col.f32.tf32.tf32.f32 "
        "{%0,%1,%2,%3},{%4,%5,%6,%7},{%8,%9},{%0,%1,%2,%3};"
        : "+f"(d[0]), "+f"(d[1]), "+f"(d[2]), "+f"(d[3])
        : "r"(a[0]), "r"(a[1]), "r"(a[2]), "r"(a[3]), "r"(b[0]), "r"(b[1]));
}

// ---------------- weight transpose BT[n][k] = round_tf32(B[k][n]) --------
__global__ void __launch_bounds__(256) k_transpose(
    const float* __restrict__ B, float* __restrict__ BT, int K, int N)
{
    __shared__ float t[32][33];
    int kb = blockIdx.y * 32, nb = blockIdx.x * 32;
    int tx = threadIdx.x & 31, ty = threadIdx.x >> 5;
    for (int i = ty; i < 32; i += 8) t[i][tx] = B[(size_t)(kb + i) * N + nb + tx];
    __syncthreads();
    for (int i = ty; i < 32; i += 8) BT[(size_t)(nb + i) * K + kb + tx] = rndt(t[tx][i]);
}

// ---------------- gather / scatter NCHW <-> token-major ----------------
__global__ void __launch_bounds__(256) k_gather(const float* __restrict__ x)
{
    __shared__ float sm[256][33];
    int tid = threadIdx.x, bi = blockIdx.x;
    int dc = bi & 7, w1 = (bi >> 3) & 7, wx = (bi >> 6) & 31, b = bi >> 11;
    const float* xb = x + ((size_t)b * 256 + dc * 32) * 65536 + (size_t)(wx * 8 + w1) * 256;
#pragma unroll
    for (int it = 0; it < 32; ++it) sm[tid][it] = xb[(size_t)it * 65536 + tid];
    __syncthreads();
#pragma unroll
    for (int it = 0; it < 32; ++it) {
        int t = it * 8 + (tid >> 5), dd = tid & 31;
        size_t tok = (((size_t)b * 32 + wx) * 32 + (t >> 3)) * 64 + w1 * 8 + (t & 7);
        g_scratch[OFF_XW + tok * 256 + dc * 32 + dd] = sm[t][dd];
    }
}
__global__ void __launch_bounds__(256) k_scatter(float* __restrict__ out)
{
    __shared__ float sm[256][33];
    int tid = threadIdx.x, bi = blockIdx.x;
    int dc = bi & 7, w1 = (bi >> 3) & 7, wx = (bi >> 6) & 31, b = bi >> 11;
#pragma unroll
    for (int it = 0; it < 32; ++it) {
        int t = it * 8 + (tid >> 5), dd = tid & 31;
        size_t tok = (((size_t)b * 32 + wx) * 32 + (t >> 3)) * 64 + w1 * 8 + (t & 7);
        sm[t][dd] = g_scratch[OFF_T + tok * 256 + dc * 32 + dd];
    }
    __syncthreads();
    float* ob = out + ((size_t)b * 256 + dc * 32) * 65536 + (size_t)(wx * 8 + w1) * 256;
#pragma unroll
    for (int it = 0; it < 32; ++it) ob[(size_t)it * 65536 + tid] = sm[tid][it];
}

// ------- LayerNorm (TWO=1: LN2(LN1(x)); TWO=0: single LN); tf32-rounds out
template <int TWO>
__global__ void __launch_bounds__(256) k_ln(
    const float* __restrict__ src, float* __restrict__ dst,
    const float* __restrict__ g1, const float* __restrict__ b1,
    const float* __restrict__ g2, const float* __restrict__ b2)
{
    __shared__ float sm[8192], sg1[256], sb1[256], sg2[256], sb2[256], st1[32][2], st2[32][2];
    int tid = threadIdx.x;
    size_t base = (size_t)blockIdx.x * 8192;
    sg1[tid] = g1[tid]; sb1[tid] = b1[tid];
    if (TWO) { sg2[tid] = g2[tid]; sb2[tid] = b2[tid]; }
#pragma unroll
    for (int it = 0; it < 32; ++it) sm[it * 256 + tid] = src[base + it * 256 + tid];
    __syncthreads();
    int warp = tid >> 5, lane = tid & 31;
#pragma unroll
    for (int j = 0; j < 4; ++j) {
        int tok = warp * 4 + j;
        float s = 0.f, ss = 0.f;
#pragma unroll
        for (int m = 0; m < 8; ++m) {
            float v = sm[tok * 256 + lane + 32 * m]; s += v; ss += v * v;
        }
#pragma unroll
        for (int o = 16; o > 0; o >>= 1) {
            s += __shfl_xor_sync(~0u, s, o); ss += __shfl_xor_sync(~0u, ss, o);
        }
        float m1 = s * (1.f / 256.f), i1 = rsqrtf(ss * (1.f / 256.f) - m1 * m1 + 1e-5f);
        if (lane == 0) { st1[tok][0] = m1; st1[tok][1] = i1; }
        if (TWO) {
            float s2 = 0.f, ss2 = 0.f;
#pragma unroll
            for (int m = 0; m < 8; ++m) {
                int d = lane + 32 * m;
                float u = (sm[tok * 256 + d] - m1) * i1 * sg1[d] + sb1[d];
                s2 += u; ss2 += u * u;
            }
#pragma unroll
            for (int o = 16; o > 0; o >>= 1) {
                s2 += __shfl_xor_sync(~0u, s2, o); ss2 += __shfl_xor_sync(~0u, ss2, o);
            }
            if (lane == 0) {
                float m2 = s2 * (1.f / 256.f);
                st2[tok][0] = m2; st2[tok][1] = rsqrtf(ss2 * (1.f / 256.f) - m2 * m2 + 1e-5f);
            }
        }
    }
    __syncthreads();
#pragma unroll
    for (int tok = 0; tok < 32; ++tok) {
        float u = (sm[tok * 256 + tid] - st1[tok][0]) * st1[tok][1] * sg1[tid] + sb1[tid];
        if (TWO) u = (u - st2[tok][0]) * st2[tok][1] * sg2[tid] + sb2[tid];
        dst[base + tok * 256 + tid] = rndt(u);
    }
}

// -------- tf32 mma.sync GEMM: C[M,N]=A[M,K]@B, BT=[N,K], A/B pre-rounded.
// tile 128x128, BK=32, 8 warps (warp 32x64), 2-stage cp.async.
// __launch_bounds__(256,2): 128-reg cap -> 2 CTAs/SM (R9 showed 134 regs = 1 CTA).
// Inner loop restructured (af hoisted, bf 2-live) to fit the cap without spill.
// EPI: 0 none | 1 +RES | 2 round(gelu(+BIAS)) | 3 +BIAS+RES
#define GEMM_SMEM 73728
template <int EPI>
__global__ void __launch_bounds__(256, 2) k_gemm_mma(
    const float* __restrict__ A, const float* __restrict__ BT,
    float* __restrict__ C, const float* __restrict__ RES,
    const float* __restrict__ BIAS, int N, int K)
{
    extern __shared__ float smf[];   // 2 stages x (A[128][36] + B[128][36])
    const int tid = threadIdx.x, lane = tid & 31, wid = tid >> 5;
    const int bm = blockIdx.y << 7, bn = blockIdx.x << 7;
    const int wr = wid & 3, wc = wid >> 2;
    const int g = lane >> 2, q = lane & 3;

    const int lrow = tid >> 3, lkq = (tid & 7) << 2;
    const float* ApG = A  + (size_t)(bm + lrow) * K + lkq;
    const float* BpG = BT + (size_t)(bn + lrow) * K + lkq;
    const uint32_t sBase = smem_u32(smf);
    const uint32_t soff = ((uint32_t)lrow * 36 + (uint32_t)lkq) * 4;

    float acc[2][8][4];
#pragma unroll
    for (int i = 0; i < 2; ++i)
#pragma unroll
        for (int j = 0; j < 8; ++j)
#pragma unroll
            for (int e = 0; e < 4; ++e) acc[i][j][e] = 0.f;

    // prefetch chunk 0
#pragma unroll
    for (int it = 0; it < 4; ++it) {
        cpa16(sBase + soff + it * 32 * 36 * 4, ApG + (size_t)(it * 32) * K);
        cpa16(sBase + 18432u + soff + it * 32 * 36 * 4, BpG + (size_t)(it * 32) * K);
    }
    asm volatile("cp.async.commit_group;" ::: "memory");

    const int nc = K >> 5;
    for (int c = 0; c < nc; ++c) {
        if (c + 1 < nc) {
            const int kc = (c + 1) << 5;
            const uint32_t st = sBase + (uint32_t)((c + 1) & 1) * 36864u;
#pragma unroll
            for (int it = 0; it < 4; ++it) {
                cpa16(st + soff + it * 32 * 36 * 4, ApG + (size_t)(it * 32) * K + kc);
                cpa16(st + 18432u + soff + it * 32 * 36 * 4, BpG + (size_t)(it * 32) * K + kc);
            }
            asm volatile("cp.async.commit_group;" ::: "memory");
            asm volatile("cp.async.wait_group 1;" ::: "memory");
        } else {
            asm volatile("cp.async.wait_group 0;" ::: "memory");
        }
        __syncthreads();

        const uint32_t* Ab = (const uint32_t*)(smf + (c & 1) * 9216) + (wr << 5) * 36;
        const uint32_t* Bb = (const uint32_t*)(smf + (c & 1) * 9216 + 4608) + (wc << 6) * 36;
#pragma unroll
        for (int ks = 0; ks < 4; ++ks) {
            const int kb = ks << 3;
            uint32_t af[2][4];
#pragma unroll
            for (int mt = 0; mt < 2; ++mt) {
                af[mt][0] = Ab[(mt * 16 + g) * 36 + kb + q];
                af[mt][1] = Ab[(mt * 16 + 8 + g) * 36 + kb + q];
                af[mt][2] = Ab[(mt * 16 + g) * 36 + kb + 4 + q];
                af[mt][3] = Ab[(mt * 16 + 8 + g) * 36 + kb + 4 + q];
            }
#pragma unroll
            for (int nt = 0; nt < 8; ++nt) {
                uint32_t bf[2];
                bf[0] = Bb[(nt * 8 + g) * 36 + kb + q];
                bf[1] = Bb[(nt * 8 + g) * 36 + kb + 4 + q];
                mma8(acc[0][nt], af[0], bf);
                mma8(acc[1][nt], af[1], bf);
            }
        }
        __syncthreads();
    }

    // epilogue
#pragma unroll
    for (int mt = 0; mt < 2; ++mt) {
#pragma unroll
        for (int nt = 0; nt < 8; ++nt) {
            int row0 = bm + (wr << 5) + mt * 16 + g;
            int col  = bn + (wc << 6) + nt * 8 + q * 2;
            float v00 = acc[mt][nt][0], v01 = acc[mt][nt][1];
            float v10 = acc[mt][nt][2], v11 = acc[mt][nt][3];
            if (EPI == 2 || EPI == 3) {
                float2 bb = *(const float2*)(BIAS + col);
                v00 += bb.x; v01 += bb.y; v10 += bb.x; v11 += bb.y;
            }
            if (EPI == 1 || EPI == 3) {
                float2 r0 = *(const float2*)(RES + (size_t)row0 * N + col);
                float2 r1 = *(const float2*)(RES + (size_t)(row0 + 8) * N + col);
                v00 += r0.x; v01 += r0.y; v10 += r1.x; v11 += r1.y;
            }
            if (EPI == 2) {
                v00 = rndt(v00 * normcdff(v00)); v01 = rndt(v01 * normcdff(v01));
                v10 = rndt(v10 * normcdff(v10)); v11 = rndt(v11 * normcdff(v11));
            }
            *(float2*)(C + (size_t)row0 * N + col)       = make_float2(v00, v01);
            *(float2*)(C + (size_t)(row0 + 8) * N + col) = make_float2(v10, v11);
        }
    }
}

// -------- windowed attention: 2 heads per pass, K transposed in SMEM ----
#define ATTN_SMEM 94752
__global__ void __launch_bounds__(256) k_attn(const float* __restrict__ rpb)
{
    extern __shared__ float sa[];
    float* sqb  = sa;           // [hh*2112 + t*33 + d]
    float* skTb = sa + 4224;    // [hh*2176 + d*68 + t]
    float* svb  = sa + 8576;    // [hh*2304 + t*36 + d]
    float* spb  = sa + 13184;   // [hh*4352 + row*68 + col]  (stride 68: float4-safe)
    float* srpb = sa + 21888;   // [1800]

    int tid = threadIdx.x;
    size_t tokbase = (size_t)blockIdx.x * 64;
    const float* qkv = g_scratch + OFF_QKV;
    float* outp = g_scratch + OFF_ATTNO;
    for (int i = tid; i < 1800; i += 256) srpb[i] = rpb[i];

    int row = tid >> 2, c = tid & 3;
    int ri = row >> 3, rj = row & 7;
    const float sc = 0.17677669529663687f;

    for (int h = 0; h < 8; h += 2) {
        __syncthreads();
#pragma unroll
        for (int m = 0; m < 4; ++m) {
            int e = m * 256 + tid;
            int t = e >> 4, rem = e & 15;
            int hh = rem >> 3, d4 = (rem & 7) << 2;
            const float* src = qkv + (tokbase + t) * 768 + (h + hh) * 32 + d4;
            float4 q4 = *(const float4*)src;
            float4 k4 = *(const float4*)(src + 256);
            float4 v4 = *(const float4*)(src + 512);
            float* sq = sqb + hh * 2112 + t * 33;
            sq[d4] = q4.x * sc; sq[d4 + 1] = q4.y * sc;
            sq[d4 + 2] = q4.z * sc; sq[d4 + 3] = q4.w * sc;
            float* sk = skTb + hh * 2176;
            sk[(d4 + 0) * 68 + t] = k4.x; sk[(d4 + 1) * 68 + t] = k4.y;
            sk[(d4 + 2) * 68 + t] = k4.z; sk[(d4 + 3) * 68 + t] = k4.w;
            *(float4*)(svb + hh * 2304 + t * 36 + d4) = v4;
        }
        __syncthreads();

#pragma unroll
        for (int hh = 0; hh < 2; ++hh) {
            const float* sq = sqb + hh * 2112 + row * 33;
            const float* sk = skTb + hh * 2176;
            float s[16];
#pragma unroll
            for (int j = 0; j < 16; ++j) s[j] = 0.f;
#pragma unroll
            for (int d = 0; d < 32; ++d) {
                float qv = sq[d];
#pragma unroll
                for (int m = 0; m < 4; ++m) {
                    float4 kk = *(const float4*)(sk + d * 68 + c * 16 + m * 4);
                    s[m * 4] += qv * kk.x; s[m * 4 + 1] += qv * kk.y;
                    s[m * 4 + 2] += qv * kk.z; s[m * 4 + 3] += qv * kk.w;
                }
            }
#pragma unroll
            for (int j = 0; j < 16; ++j) {
                int col = c * 16 + j;
                s[j] += srpb[((ri - (col >> 3) + 7) * 15 + (rj - (col & 7) + 7)) * 8 + h + hh];
            }
            float mx = s[0];
#pragma unroll
            for (int j = 1; j < 16; ++j) mx = fmaxf(mx, s[j]);
            mx = fmaxf(mx, __shfl_xor_sync(~0u, mx, 1));
            mx = fmaxf(mx, __shfl_xor_sync(~0u, mx, 2));
            float sum = 0.f;
#pragma unroll
            for (int j = 0; j < 16; ++j) { s[j] = __expf(s[j] - mx); sum += s[j]; }
            sum += __shfl_xor_sync(~0u, sum, 1);
            sum += __shfl_xor_sync(~0u, sum, 2);
            float inv = 1.f / sum;
            float* sp = spb + hh * 4352 + row * 68;
#pragma unroll
            for (int m = 0; m < 4; ++m)
                *(float4*)(sp + c * 16 + m * 4) =
                    make_float4(s[m * 4] * inv, s[m * 4 + 1] * inv,
                                s[m * 4 + 2] * inv, s[m * 4 + 3] * inv);
        }
        __syncthreads();

#pragma unroll
        for (int hh = 0; hh < 2; ++hh) {
            const float* sp = spb + hh * 4352 + row * 68;
            const float* sv = svb + hh * 2304;
            float o[8];
#pragma unroll
            for (int dd = 0; dd < 8; ++dd) o[dd] = 0.f;
#pragma unroll
            for (int j4 = 0; j4 < 16; ++j4) {
                float4 p4 = *(const float4*)(sp + j4 * 4);
                const float* v0 = sv + (j4 * 4) * 36 + c * 8;
                float4 a0 = *(const float4*)v0,        a1 = *(const float4*)(v0 + 4);
                float4 b0 = *(const float4*)(v0 + 36), b1 = *(const float4*)(v0 + 40);
                float4 c0 = *(const float4*)(v0 + 72), c1 = *(const float4*)(v0 + 76);
                float4 d0 = *(const float4*)(v0 + 108), d1 = *(const float4*)(v0 + 112);
                o[0] += p4.x * a0.x + p4.y * b0.x + p4.z * c0.x + p4.w * d0.x;
                o[1] += p4.x * a0.y + p4.y * b0.y + p4.z * c0.y + p4.w * d0.y;
                o[2] += p4.x * a0.z + p4.y * b0.z + p4.z * c0.z + p4.w * d0.z;
                o[3] += p4.x * a0.w + p4.y * b0.w + p4.z * c0.w + p4.w * d0.w;
                o[4] += p4.x * a1.x + p4.y * b1.x + p4.z * c1.x + p4.w * d1.x;
                o[5] += p4.x * a1.y + p4.y * b1.y + p4.z * c1.y + p4.w * d1.y;
                o[6] += p4.x * a1.z + p4.y * b1.z + p4.z * c1.z + p4.w * d1.z;
                o[7] += p4.x * a1.w + p4.y * b1.w + p4.z * c1.w + p4.w * d1.w;
            }
            float* dst = outp + (tokbase + row) * 256 + (h + hh) * 32 + c * 8;
            *(float4*)dst =
                make_float4(rndt(o[0]), rndt(o[1]), rndt(o[2]), rndt(o[3]));
            *(float4*)(dst + 4) =
                make_float4(rndt(o[4]), rndt(o[5]), rndt(o[6]), rndt(o[7]));
        }
    }
}

// ---------------- host launcher ----------------
extern "C" void kernel_launch(void* const* d_in, const int* in_sizes, int n_in,
                              void* d_out, int out_size)
{
    const float* x     = (const float*)d_in[0];
    const float* ln1_g = (const float*)d_in[1];
    const float* ln1_b = (const float*)d_in[2];
    const float* ln2_g = (const float*)d_in[3];
    const float* ln2_b = (const float*)d_in[4];
    const float* w_qkv = (const float*)d_in[5];
    const float* w_out = (const float*)d_in[6];
    const float* rpb   = (const float*)d_in[7];
    const float* ln3_g = (const float*)d_in[8];
    const float* ln3_b = (const float*)d_in[9];
    const float* w1    = (const float*)d_in[10];
    const float* b1    = (const float*)d_in[11];
    const float* w2    = (const float*)d_in[12];
    const float* b2    = (const float*)d_in[13];
    float* out = (float*)d_out;

    float* S = nullptr;
    cudaGetSymbolAddress((void**)&S, g_scratch);

    cudaFuncSetAttribute(k_gemm_mma<0>, cudaFuncAttributeMaxDynamicSharedMemorySize, GEMM_SMEM);
    cudaFuncSetAttribute(k_gemm_mma<1>, cudaFuncAttributeMaxDynamicSharedMemorySize, GEMM_SMEM);
    cudaFuncSetAttribute(k_gemm_mma<2>, cudaFuncAttributeMaxDynamicSharedMemorySize, GEMM_SMEM);
    cudaFuncSetAttribute(k_gemm_mma<3>, cudaFuncAttributeMaxDynamicSharedMemorySize, GEMM_SMEM);
    cudaFuncSetAttribute(k_attn, cudaFuncAttributeMaxDynamicSharedMemorySize, ATTN_SMEM);

    // order chosen so the profiled launch (#4) is the qkv GEMM
    k_gather<<<4096, 256>>>(x);                                              // 1
    k_ln<1><<<4096, 256>>>(S + OFF_XW, S + OFF_T, ln1_g, ln1_b, ln2_g, ln2_b); // 2
    k_transpose<<<dim3(24, 8), 256>>>(w_qkv, S + OFF_BT_QKV, 256, 768);      // 3
    k_gemm_mma<0><<<dim3(6, 1024), 256, GEMM_SMEM>>>(                        // 4
        S + OFF_T, S + OFF_BT_QKV, S + OFF_QKV, S, S, 768, 256);
    k_transpose<<<dim3(8, 8), 256>>>(w_out, S + OFF_BT_OUT, 256, 256);       // 5
    k_transpose<<<dim3(32, 8), 256>>>(w1, S + OFF_BT_W1, 256, 1024);         // 6
    k_transpose<<<dim3(8, 32), 256>>>(w2, S + OFF_BT_W2, 1024, 256);         // 7
    k_attn<<<2048, 256, ATTN_SMEM>>>(rpb);                                   // 8
    k_gemm_mma<1><<<dim3(2, 1024), 256, GEMM_SMEM>>>(
        S + OFF_ATTNO, S + OFF_BT_OUT, S + OFF_XW2, S + OFF_XW, S, 256, 256);
    k_ln<0><<<4096, 256>>>(S + OFF_XW2, S + OFF_F, ln3_g, ln3_b, ln3_g, ln3_b);
    k_gemm_mma<2><<<dim3(8, 1024), 256, GEMM_SMEM>>>(
        S + OFF_F, S + OFF_BT_W1, S + OFF_H, S, b1, 1024, 256);
    k_gemm_mma<3><<<dim3(2, 1024), 256, GEMM_SMEM>>>(
        S + OFF_H, S + OFF_BT_W2, S + OFF_T, S + OFF_XW2, b2, 256, 1024);
    k_scatter<<<4096, 256>>>(out);
}